// round 8
// baseline (speedup 1.0000x reference)
#include <cuda_runtime.h>
#include <cuda_fp16.h>
#include <stdint.h>

#define BATCH 16
#define SEQ 256
#define DIM 256
#define MAT 65536
#define NTOT 1048576
#define ABAR 0.042323627f   // 1/(1+sqrt(512))

// ---------------------------------------------------------------------------
// Device-global scratch
// ---------------------------------------------------------------------------
__device__ float g_x1att[NTOT];
__device__ float g_x2att[NTOT];
__device__ float g_n1[BATCH*SEQ];
__device__ float g_n2[BATCH*SEQ];
__device__ float g_sum[4];     // 0=x1, 1=x1_att, 2=x2, 3=x2_att
__device__ float g_sumsq[4];
__device__ float g_corr[DIM];  // ABAR*rowsum(W)+bias
__device__ __half g_x1h[NTOT];
__device__ __half g_x2h[NTOT];
__device__ __half g_Wh[SEQ*DIM];

// ---------------------------------------------------------------------------
// Portable-ISA helpers (sm_80+)
// ---------------------------------------------------------------------------
__device__ __forceinline__ uint32_t smem_to_u32(const void* p) {
    uint32_t a;
    asm("{ .reg .u64 t; cvta.to.shared.u64 t, %1; cvt.u32.u64 %0, t; }" : "=r"(a) : "l"(p));
    return a;
}
__device__ __forceinline__ void ldsm4(uint32_t* r, uint32_t addr) {
    asm volatile("ldmatrix.sync.aligned.m8n8.x4.shared.b16 {%0,%1,%2,%3}, [%4];"
                 : "=r"(r[0]), "=r"(r[1]), "=r"(r[2]), "=r"(r[3]) : "r"(addr));
}
__device__ __forceinline__ void mma_fp16(float* c, const uint32_t* a, const uint32_t* b) {
    asm volatile("mma.sync.aligned.m16n8k16.row.col.f32.f16.f16.f32 "
                 "{%0,%1,%2,%3}, {%4,%5,%6,%7}, {%8,%9}, {%0,%1,%2,%3};"
                 : "+f"(c[0]), "+f"(c[1]), "+f"(c[2]), "+f"(c[3])
                 : "r"(a[0]), "r"(a[1]), "r"(a[2]), "r"(a[3]), "r"(b[0]), "r"(b[1]));
}
__device__ __forceinline__ void cp16(uint32_t saddr, const void* g) {
    asm volatile("cp.async.cg.shared.global [%0], [%1], 16;" :: "r"(saddr), "l"(g));
}
#define CP_COMMIT() asm volatile("cp.async.commit_group;" ::: "memory")
#define CP_WAIT1()  asm volatile("cp.async.wait_group 1;" ::: "memory")
#define CP_WAIT0()  asm volatile("cp.async.wait_group 0;" ::: "memory")

// SMEM geometry for the fused kernel (64-row blocks)
#define PR 528                  // pitch of 256-half rows (33x16B, conflict-free)
#define PB 144                  // pitch of 64-half rows
#define BTILE (256 * PB)        // 36864 bytes: one B chunk [256 n][64 k]
#define OFF_SNC   0             // 256 floats
#define OFF_SNR   1024          // 64 floats
#define OFF_CORR  1280          // 256 floats
#define OFF_SR    2304          // 64 x PR = 33792
#define OFF_SAT   36096         // 64 x PR = 33792
#define OFF_SD    69888         // 2 x BTILE = 73728
#define OFF_STAT  143616        // 32 floats
#define F_SMEM    143744

// ---------------------------------------------------------------------------
__global__ void k_zero() {
    int t = threadIdx.x;
    if (t < 4) { g_sum[t] = 0.f; g_sumsq[t] = 0.f; }
}

// ---------------------------------------------------------------------------
// k_prep: blocks [0,512) x1: norms+stats+fp16.  [512,1024) x2.
//         [1024,1088) W fp16 convert.  [1088,1120) corr = ABAR*rowsum(W)+bias
// ---------------------------------------------------------------------------
__global__ void __launch_bounds__(256) k_prep(const float* __restrict__ x1,
                                              const float* __restrict__ x2,
                                              const float* __restrict__ W,
                                              const float* __restrict__ bias) {
    int blk = blockIdx.x;
    int t = threadIdx.x;
    if (blk >= 1088) {   // corr rows
        int warp = t >> 5, lane = t & 31;
        int o = (blk - 1088) * 8 + warp;
        float s = 0.f;
#pragma unroll
        for (int c = 0; c < 8; c++) s += W[o * SEQ + lane + c * 32];
#pragma unroll
        for (int off = 16; off; off >>= 1) s += __shfl_xor_sync(0xffffffffu, s, off);
        if (lane == 0) g_corr[o] = ABAR * s + bias[o];
        return;
    }
    if (blk >= 1024) {   // W fp16 (vectorized)
        int base = (blk - 1024) * 1024 + t * 4;
        float4 v = *(const float4*)&W[base];
        __half2 h0 = __floats2half2_rn(v.x, v.y);
        __half2 h1 = __floats2half2_rn(v.z, v.w);
        *(uint2*)&g_Wh[base] = make_uint2(*(uint32_t*)&h0, *(uint32_t*)&h1);
        return;
    }
    const float* X;
    float* Nrm;
    __half* Xh;
    int ch;
    if (blk < 512) { X = x1; Nrm = g_n1; Xh = g_x1h; ch = 0; }
    else           { X = x2; Nrm = g_n2; Xh = g_x2h; blk -= 512; ch = 2; }
    int warp = t >> 5, lane = t & 31;
    int row = blk * 8 + warp;
    const float4* p4 = (const float4*)(X + row * DIM);
    float4 v0 = p4[lane];
    float4 v1 = p4[lane + 32];
    float s = v0.x + v0.y + v0.z + v0.w + v1.x + v1.y + v1.z + v1.w;
    float q = v0.x*v0.x + v0.y*v0.y + v0.z*v0.z + v0.w*v0.w
            + v1.x*v1.x + v1.y*v1.y + v1.z*v1.z + v1.w*v1.w;
    {
        __half2 a0 = __floats2half2_rn(v0.x, v0.y);
        __half2 a1 = __floats2half2_rn(v0.z, v0.w);
        __half2 b0 = __floats2half2_rn(v1.x, v1.y);
        __half2 b1 = __floats2half2_rn(v1.z, v1.w);
        uint2* dst = (uint2*)(Xh + row * DIM);
        dst[lane]      = make_uint2(*(uint32_t*)&a0, *(uint32_t*)&a1);
        dst[lane + 32] = make_uint2(*(uint32_t*)&b0, *(uint32_t*)&b1);
    }
#pragma unroll
    for (int off = 16; off; off >>= 1) {
        s += __shfl_xor_sync(0xffffffffu, s, off);
        q += __shfl_xor_sync(0xffffffffu, q, off);
    }
    __shared__ float bs[8], bq[8];
    if (lane == 0) { Nrm[row] = q; bs[warp] = s; bq[warp] = q; }
    __syncthreads();
    if (t == 0) {
        float S = 0.f, Q = 0.f;
#pragma unroll
        for (int w = 0; w < 8; w++) { S += bs[w]; Q += bq[w]; }
        atomicAdd(&g_sum[ch], S);
        atomicAdd(&g_sumsq[ch], Q);
    }
}

// ---------------------------------------------------------------------------
// k_att: FUSED attention + projection, 64-row blocks.
// grid (4, 32): x = j-block (64 rows), y = b*2+which.
//   which=0: rows from x2, cols from x1 -> x2_att rows (ch 3)
//   which=1: rows from x1, cols from x2 -> x1_att rows (ch 1)
// Stage 1: delta[r][i] (M=64,N=256,K=256) -> SMEM strip fp16
// Stage 2: out[r][o] = delta @ W^T + corr  (M=64,N=256,K=256)
// 512 threads, 16 warps: m = (wid&1)*32, n = (wid>>1)*32. Warp tile 32x32.
// Continuous cp.async double-buffer pipeline: C chunks then W chunks.
// ---------------------------------------------------------------------------
__global__ void __launch_bounds__(512, 1) k_att() {
    extern __shared__ char smem[];
    uint32_t sb = smem_to_u32(smem);
    float* snc   = (float*)(smem + OFF_SNC);
    float* snr   = (float*)(smem + OFF_SNR);
    float* scorr = (float*)(smem + OFF_CORR);
    int t = threadIdx.x, lane = t & 31, wid = t >> 5;
    int jb = blockIdx.x;
    int bz = blockIdx.y, b = bz >> 1, which = bz & 1;

    const __half* R = (which ? g_x1h : g_x2h) + b * MAT + jb * 64 * DIM;
    const __half* C = (which ? g_x2h : g_x1h) + b * MAT;
    const float* NR = (which ? g_n1 : g_n2) + b * SEQ + jb * 64;
    const float* NC = (which ? g_n2 : g_n1) + b * SEQ;
    float* out = (which ? g_x1att : g_x2att) + b * MAT + jb * 64 * DIM;
    int ch = which ? 1 : 3;

    if (t < 256) { snc[t] = NC[t]; scorr[t] = g_corr[t]; }
    else if (t < 320) snr[t - 256] = NR[t - 256];

    const uint32_t sR  = sb + OFF_SR;
    const uint32_t sAt = sb + OFF_SAT;
    const uint32_t sD  = sb + OFF_SD;

    // B-chunk loader: [256 n][64 k] from src (row pitch 256 halfs): 2048 cp16
    auto loadB = [&](const __half* src, int kc, int buf) {
#pragma unroll
        for (int s = 0; s < 4; s++) {
            int seg = t + s * 512;
            int row = seg >> 3, c = seg & 7;
            cp16(sD + (uint32_t)(buf * BTILE + row * PB + c * 16),
                 src + row * SEQ + kc * 64 + c * 8);
        }
    };

    // R strip [64][256] (2048 cp16) + first C chunk = group 0
#pragma unroll
    for (int s = 0; s < 4; s++) {
        int seg = t + s * 512;
        int row = seg >> 5, c = seg & 31;
        cp16(sR + (uint32_t)(row * PR + c * 16), R + row * DIM + c * 8);
    }
    loadB(C, 0, 0);
    CP_COMMIT();

    int m0 = (wid & 1) * 32, n0 = (wid >> 1) * 32;
    float acc[2][4][4] = {};

    // ---- stage 1: 4 K-chunks over dim ----
    for (int kc = 0; kc < 4; kc++) {
        if (kc < 3) loadB(C, kc + 1, (kc + 1) & 1);
        else        loadB(g_Wh, 0, 0);          // prefetch W chunk 0
        CP_COMMIT();
        CP_WAIT1();
        __syncthreads();
        uint32_t bufB = sD + (kc & 1) * BTILE;
#pragma unroll
        for (int kk = 0; kk < 4; kk++) {
            uint32_t af[2][4];
#pragma unroll
            for (int mi = 0; mi < 2; mi++)
                ldsm4(af[mi], sR + (uint32_t)((m0 + mi * 16 + (lane & 15)) * PR
                                              + kc * 128 + kk * 32 + (lane >> 4) * 16));
            uint32_t bf[4][2];
#pragma unroll
            for (int np = 0; np < 2; np++) {
                uint32_t r[4];
                ldsm4(r, bufB + (uint32_t)((n0 + np * 16 + (lane & 7) + ((lane >> 4) & 1) * 8) * PB
                                            + kk * 32 + ((lane >> 3) & 1) * 16));
                bf[np * 2][0] = r[0]; bf[np * 2][1] = r[1];
                bf[np * 2 + 1][0] = r[2]; bf[np * 2 + 1][1] = r[3];
            }
#pragma unroll
            for (int mi = 0; mi < 2; mi++)
#pragma unroll
                for (int ni = 0; ni < 4; ni++)
                    mma_fp16(acc[mi][ni], af[mi], bf[ni]);
        }
        __syncthreads();
    }

    // ---- stage-1 epilogue: delta -> sAt, reset acc ----
#pragma unroll
    for (int mi = 0; mi < 2; mi++) {
#pragma unroll
        for (int ni = 0; ni < 4; ni++) {
#pragma unroll
            for (int h = 0; h < 2; h++) {
                int row = m0 + mi * 16 + (lane >> 2) + h * 8;
                int col = n0 + ni * 8 + (lane & 3) * 2;
                float e0 = fmaxf(snr[row] + snc[col]     - 2.f * acc[mi][ni][h * 2],     0.f);
                float e1 = fmaxf(snr[row] + snc[col + 1] - 2.f * acc[mi][ni][h * 2 + 1], 0.f);
                float a0 = 1.f / (sqrtf(e0 + 1e-6f) + 1.f) - ABAR;
                float a1 = 1.f / (sqrtf(e1 + 1e-6f) + 1.f) - ABAR;
                *(__half2*)(smem + OFF_SAT + row * PR + col * 2) = __floats2half2_rn(a0, a1);
                acc[mi][ni][h * 2] = 0.f;
                acc[mi][ni][h * 2 + 1] = 0.f;
            }
        }
    }
    __syncthreads();

    // ---- stage 2: 4 K-chunks over i (A = sAt, B = W chunks) ----
    for (int kc = 0; kc < 4; kc++) {
        if (kc < 3) loadB(g_Wh, kc + 1, (kc + 1) & 1);
        CP_COMMIT();
        if (kc < 3) CP_WAIT1(); else CP_WAIT0();
        __syncthreads();
        uint32_t bufB = sD + (kc & 1) * BTILE;
#pragma unroll
        for (int kk = 0; kk < 4; kk++) {
            uint32_t af[2][4];
#pragma unroll
            for (int mi = 0; mi < 2; mi++)
                ldsm4(af[mi], sAt + (uint32_t)((m0 + mi * 16 + (lane & 15)) * PR
                                               + kc * 128 + kk * 32 + (lane >> 4) * 16));
            uint32_t bf[4][2];
#pragma unroll
            for (int np = 0; np < 2; np++) {
                uint32_t r[4];
                ldsm4(r, bufB + (uint32_t)((n0 + np * 16 + (lane & 7) + ((lane >> 4) & 1) * 8) * PB
                                            + kk * 32 + ((lane >> 3) & 1) * 16));
                bf[np * 2][0] = r[0]; bf[np * 2][1] = r[1];
                bf[np * 2 + 1][0] = r[2]; bf[np * 2 + 1][1] = r[3];
            }
#pragma unroll
            for (int mi = 0; mi < 2; mi++)
#pragma unroll
                for (int ni = 0; ni < 4; ni++)
                    mma_fp16(acc[mi][ni], af[mi], bf[ni]);
        }
        __syncthreads();
    }

    // ---- stage-2 epilogue: +corr, fp32 store, BN stats ----
    float ps = 0.f, pq = 0.f;
#pragma unroll
    for (int mi = 0; mi < 2; mi++) {
#pragma unroll
        for (int ni = 0; ni < 4; ni++) {
#pragma unroll
            for (int h = 0; h < 2; h++) {
                int row = m0 + mi * 16 + (lane >> 2) + h * 8;
                int col = n0 + ni * 8 + (lane & 3) * 2;
                float v0 = acc[mi][ni][h * 2]     + scorr[col];
                float v1 = acc[mi][ni][h * 2 + 1] + scorr[col + 1];
                *(float2*)&out[row * DIM + col] = make_float2(v0, v1);
                ps += v0 + v1;
                pq += v0 * v0 + v1 * v1;
            }
        }
    }
#pragma unroll
    for (int off = 16; off; off >>= 1) {
        ps += __shfl_xor_sync(0xffffffffu, ps, off);
        pq += __shfl_xor_sync(0xffffffffu, pq, off);
    }
    float* ws = (float*)(smem + OFF_STAT);
    float* wq = ws + 16;
    if (lane == 0) { ws[wid] = ps; wq[wid] = pq; }
    __syncthreads();
    if (t == 0) {
        float S = 0.f, Q = 0.f;
#pragma unroll
        for (int w = 0; w < 16; w++) { S += ws[w]; Q += wq[w]; }
        atomicAdd(&g_sum[ch], S);
        atomicAdd(&g_sumsq[ch], Q);
    }
}

// ---------------------------------------------------------------------------
// k_bn: apply training-mode BN, write both outputs.
// 16 elements (4 float4) per thread for MLP=4. grid 1024 x 256.
// out layout: [which_out(2)][b(16)][c(2)][s(256)][d(256)]
// ---------------------------------------------------------------------------
__global__ void __launch_bounds__(256) k_bn(const float* __restrict__ x1,
                                            const float* __restrict__ x2,
                                            const float* __restrict__ gamma,
                                            const float* __restrict__ beta,
                                            float* __restrict__ out) {
    int idx = blockIdx.x * blockDim.x + threadIdx.x;
    int e = idx << 4;                  // 16 consecutive elements
    int which = e >> 21;
    int rem = e & ((1 << 21) - 1);
    int bb = rem >> 17;
    int c = (rem >> 16) & 1;
    int pos = rem & 65535;
    const float* src;
    int ch;
    if (which == 0) { src = c ? g_x1att : x1; ch = c ? 1 : 0; }
    else            { src = c ? g_x2att : x2; ch = c ? 3 : 2; }
    const float Ninv = 1.0f / (float)NTOT;
    float mean = g_sum[ch] * Ninv;
    float var = g_sumsq[ch] * Ninv - mean * mean;
    float sc = gamma[c] * rsqrtf(var + 1e-5f);
    float sh = beta[c] - mean * sc;
    const float4* s4 = (const float4*)&src[bb * MAT + pos];
    float4* o4 = (float4*)&out[e];
    float4 v[4];
#pragma unroll
    for (int i = 0; i < 4; i++) v[i] = s4[i];
#pragma unroll
    for (int i = 0; i < 4; i++) {
        float4 o;
        o.x = v[i].x * sc + sh;
        o.y = v[i].y * sc + sh;
        o.z = v[i].z * sc + sh;
        o.w = v[i].w * sc + sh;
        o4[i] = o;
    }
}

// ---------------------------------------------------------------------------
extern "C" void kernel_launch(void* const* d_in, const int* in_sizes, int n_in,
                              void* d_out, int out_size) {
    const float* x1    = (const float*)d_in[0];
    const float* x2    = (const float*)d_in[1];
    const float* W     = (const float*)d_in[2];
    const float* bias  = (const float*)d_in[3];
    const float* gamma = (const float*)d_in[4];
    const float* beta  = (const float*)d_in[5];
    float* out = (float*)d_out;

    cudaFuncSetAttribute(k_att, cudaFuncAttributeMaxDynamicSharedMemorySize, F_SMEM);

    k_zero<<<1, 32>>>();
    k_prep<<<1120, 256>>>(x1, x2, W, bias);
    k_att<<<dim3(4, 32), 512, F_SMEM>>>();
    k_bn<<<1024, 256>>>(x1, x2, gamma, beta, out);
}

// round 9
// speedup vs baseline: 1.0749x; 1.0749x over previous
#include <cuda_runtime.h>
#include <cuda_fp16.h>
#include <stdint.h>

#define BATCH 16
#define SEQ 256
#define DIM 256
#define MAT 65536
#define NTOT 1048576
#define ABAR 0.042323627f   // 1/(1+sqrt(512))

// ---------------------------------------------------------------------------
// Device-global scratch (no atomics anywhere: fixed-slot partial sums)
// ---------------------------------------------------------------------------
__device__ float g_x1att[NTOT];
__device__ float g_x2att[NTOT];
__device__ float g_n1[BATCH*SEQ];
__device__ float g_n2[BATCH*SEQ];
__device__ float g_corr[DIM];  // ABAR*rowsum(W)+bias
__device__ __half g_x1h[NTOT];
__device__ __half g_x2h[NTOT];
__device__ __half g_Wh[SEQ*DIM];
// partial BN stats
__device__ float g_p1s[512], g_p1q[512];   // x1 (ch0), one per prep block
__device__ float g_p2s[512], g_p2q[512];   // x2 (ch2)
__device__ float g_pa1s[64], g_pa1q[64];   // x1_att (ch1), one per k_att CTA
__device__ float g_pa3s[64], g_pa3q[64];   // x2_att (ch3)

// ---------------------------------------------------------------------------
// Portable-ISA helpers (sm_80+)
// ---------------------------------------------------------------------------
__device__ __forceinline__ uint32_t smem_to_u32(const void* p) {
    uint32_t a;
    asm("{ .reg .u64 t; cvta.to.shared.u64 t, %1; cvt.u32.u64 %0, t; }" : "=r"(a) : "l"(p));
    return a;
}
__device__ __forceinline__ void ldsm4(uint32_t* r, uint32_t addr) {
    asm volatile("ldmatrix.sync.aligned.m8n8.x4.shared.b16 {%0,%1,%2,%3}, [%4];"
                 : "=r"(r[0]), "=r"(r[1]), "=r"(r[2]), "=r"(r[3]) : "r"(addr));
}
__device__ __forceinline__ void mma_fp16(float* c, const uint32_t* a, const uint32_t* b) {
    asm volatile("mma.sync.aligned.m16n8k16.row.col.f32.f16.f16.f32 "
                 "{%0,%1,%2,%3}, {%4,%5,%6,%7}, {%8,%9}, {%0,%1,%2,%3};"
                 : "+f"(c[0]), "+f"(c[1]), "+f"(c[2]), "+f"(c[3])
                 : "r"(a[0]), "r"(a[1]), "r"(a[2]), "r"(a[3]), "r"(b[0]), "r"(b[1]));
}
__device__ __forceinline__ void cp16(uint32_t saddr, const void* g) {
    asm volatile("cp.async.cg.shared.global [%0], [%1], 16;" :: "r"(saddr), "l"(g));
}
#define CP_COMMIT() asm volatile("cp.async.commit_group;" ::: "memory")
#define CP_WAIT1()  asm volatile("cp.async.wait_group 1;" ::: "memory")
#define CP_WAIT0()  asm volatile("cp.async.wait_group 0;" ::: "memory")

// SMEM geometry for the fused kernel (64-row blocks)
#define PR 528                  // pitch of 256-half rows (33x16B, conflict-free)
#define PB 144                  // pitch of 64-half rows
#define BTILE (256 * PB)        // 36864 bytes: one B chunk [256 n][64 k]
#define OFF_SNC   0             // 256 floats
#define OFF_SNR   1024          // 64 floats
#define OFF_CORR  1280          // 256 floats
#define OFF_SR    2304          // 64 x PR = 33792
#define OFF_SAT   36096         // 64 x PR = 33792
#define OFF_SD    69888         // 2 x BTILE = 73728
#define OFF_STAT  143616        // 32 floats
#define F_SMEM    143744

// ---------------------------------------------------------------------------
// k_prep: blocks [0,512) x1: norms+partial stats+fp16.  [512,1024) x2.
//         [1024,1088) W fp16 convert.  [1088,1120) corr = ABAR*rowsum(W)+bias
// ---------------------------------------------------------------------------
__global__ void __launch_bounds__(256) k_prep(const float* __restrict__ x1,
                                              const float* __restrict__ x2,
                                              const float* __restrict__ W,
                                              const float* __restrict__ bias) {
    int blk = blockIdx.x;
    int t = threadIdx.x;
    if (blk >= 1088) {   // corr rows
        int warp = t >> 5, lane = t & 31;
        int o = (blk - 1088) * 8 + warp;
        float s = 0.f;
#pragma unroll
        for (int c = 0; c < 8; c++) s += W[o * SEQ + lane + c * 32];
#pragma unroll
        for (int off = 16; off; off >>= 1) s += __shfl_xor_sync(0xffffffffu, s, off);
        if (lane == 0) g_corr[o] = ABAR * s + bias[o];
        return;
    }
    if (blk >= 1024) {   // W fp16 (vectorized)
        int base = (blk - 1024) * 1024 + t * 4;
        float4 v = *(const float4*)&W[base];
        __half2 h0 = __floats2half2_rn(v.x, v.y);
        __half2 h1 = __floats2half2_rn(v.z, v.w);
        *(uint2*)&g_Wh[base] = make_uint2(*(uint32_t*)&h0, *(uint32_t*)&h1);
        return;
    }
    const float* X;
    float* Nrm;
    __half* Xh;
    float* Ps;
    float* Pq;
    if (blk < 512) { X = x1; Nrm = g_n1; Xh = g_x1h; Ps = g_p1s; Pq = g_p1q; }
    else           { X = x2; Nrm = g_n2; Xh = g_x2h; blk -= 512; Ps = g_p2s; Pq = g_p2q; }
    int warp = t >> 5, lane = t & 31;
    int row = blk * 8 + warp;
    const float4* p4 = (const float4*)(X + row * DIM);
    float4 v0 = p4[lane];
    float4 v1 = p4[lane + 32];
    float s = v0.x + v0.y + v0.z + v0.w + v1.x + v1.y + v1.z + v1.w;
    float q = v0.x*v0.x + v0.y*v0.y + v0.z*v0.z + v0.w*v0.w
            + v1.x*v1.x + v1.y*v1.y + v1.z*v1.z + v1.w*v1.w;
    {
        __half2 a0 = __floats2half2_rn(v0.x, v0.y);
        __half2 a1 = __floats2half2_rn(v0.z, v0.w);
        __half2 b0 = __floats2half2_rn(v1.x, v1.y);
        __half2 b1 = __floats2half2_rn(v1.z, v1.w);
        uint2* dst = (uint2*)(Xh + row * DIM);
        dst[lane]      = make_uint2(*(uint32_t*)&a0, *(uint32_t*)&a1);
        dst[lane + 32] = make_uint2(*(uint32_t*)&b0, *(uint32_t*)&b1);
    }
#pragma unroll
    for (int off = 16; off; off >>= 1) {
        s += __shfl_xor_sync(0xffffffffu, s, off);
        q += __shfl_xor_sync(0xffffffffu, q, off);
    }
    __shared__ float bs[8], bq[8];
    if (lane == 0) { Nrm[row] = q; bs[warp] = s; bq[warp] = q; }
    __syncthreads();
    if (t == 0) {
        float S = 0.f, Q = 0.f;
#pragma unroll
        for (int w = 0; w < 8; w++) { S += bs[w]; Q += bq[w]; }
        Ps[blk] = S;
        Pq[blk] = Q;
    }
}

// ---------------------------------------------------------------------------
// k_att: FUSED attention + projection, 64-row blocks.
// grid (4, 32): x = j-block (64 rows), y = b*2+which.
//   which=0: rows from x2, cols from x1 -> x2_att rows (ch 3)
//   which=1: rows from x1, cols from x2 -> x1_att rows (ch 1)
// Stage 1: delta[r][i] (M=64,N=256,K=256) -> SMEM strip fp16
// Stage 2: out[r][o] = delta @ W^T + corr  (M=64,N=256,K=256)
// 512 threads, 16 warps: m = (wid&1)*32, n = (wid>>1)*32. Warp tile 32x32.
// ---------------------------------------------------------------------------
__global__ void __launch_bounds__(512, 1) k_att() {
    extern __shared__ char smem[];
    uint32_t sb = smem_to_u32(smem);
    float* snc   = (float*)(smem + OFF_SNC);
    float* snr   = (float*)(smem + OFF_SNR);
    float* scorr = (float*)(smem + OFF_CORR);
    int t = threadIdx.x, lane = t & 31, wid = t >> 5;
    int jb = blockIdx.x;
    int bz = blockIdx.y, b = bz >> 1, which = bz & 1;

    const __half* R = (which ? g_x1h : g_x2h) + b * MAT + jb * 64 * DIM;
    const __half* C = (which ? g_x2h : g_x1h) + b * MAT;
    const float* NR = (which ? g_n1 : g_n2) + b * SEQ + jb * 64;
    const float* NC = (which ? g_n2 : g_n1) + b * SEQ;
    float* out = (which ? g_x1att : g_x2att) + b * MAT + jb * 64 * DIM;

    if (t < 256) { snc[t] = NC[t]; scorr[t] = g_corr[t]; }
    else if (t < 320) snr[t - 256] = NR[t - 256];

    const uint32_t sR  = sb + OFF_SR;
    const uint32_t sAt = sb + OFF_SAT;
    const uint32_t sD  = sb + OFF_SD;

    auto loadB = [&](const __half* src, int kc, int buf) {
#pragma unroll
        for (int s = 0; s < 4; s++) {
            int seg = t + s * 512;
            int row = seg >> 3, c = seg & 7;
            cp16(sD + (uint32_t)(buf * BTILE + row * PB + c * 16),
                 src + row * SEQ + kc * 64 + c * 8);
        }
    };

#pragma unroll
    for (int s = 0; s < 4; s++) {
        int seg = t + s * 512;
        int row = seg >> 5, c = seg & 31;
        cp16(sR + (uint32_t)(row * PR + c * 16), R + row * DIM + c * 8);
    }
    loadB(C, 0, 0);
    CP_COMMIT();

    int m0 = (wid & 1) * 32, n0 = (wid >> 1) * 32;
    float acc[2][4][4] = {};

    // ---- stage 1 ----
    for (int kc = 0; kc < 4; kc++) {
        if (kc < 3) loadB(C, kc + 1, (kc + 1) & 1);
        else        loadB(g_Wh, 0, 0);          // prefetch W chunk 0
        CP_COMMIT();
        CP_WAIT1();
        __syncthreads();
        uint32_t bufB = sD + (kc & 1) * BTILE;
#pragma unroll
        for (int kk = 0; kk < 4; kk++) {
            uint32_t af[2][4];
#pragma unroll
            for (int mi = 0; mi < 2; mi++)
                ldsm4(af[mi], sR + (uint32_t)((m0 + mi * 16 + (lane & 15)) * PR
                                              + kc * 128 + kk * 32 + (lane >> 4) * 16));
            uint32_t bf[4][2];
#pragma unroll
            for (int np = 0; np < 2; np++) {
                uint32_t r[4];
                ldsm4(r, bufB + (uint32_t)((n0 + np * 16 + (lane & 7) + ((lane >> 4) & 1) * 8) * PB
                                            + kk * 32 + ((lane >> 3) & 1) * 16));
                bf[np * 2][0] = r[0]; bf[np * 2][1] = r[1];
                bf[np * 2 + 1][0] = r[2]; bf[np * 2 + 1][1] = r[3];
            }
#pragma unroll
            for (int mi = 0; mi < 2; mi++)
#pragma unroll
                for (int ni = 0; ni < 4; ni++)
                    mma_fp16(acc[mi][ni], af[mi], bf[ni]);
        }
        __syncthreads();
    }

    // ---- stage-1 epilogue: delta -> sAt ----
#pragma unroll
    for (int mi = 0; mi < 2; mi++) {
#pragma unroll
        for (int ni = 0; ni < 4; ni++) {
#pragma unroll
            for (int h = 0; h < 2; h++) {
                int row = m0 + mi * 16 + (lane >> 2) + h * 8;
                int col = n0 + ni * 8 + (lane & 3) * 2;
                float e0 = fmaxf(snr[row] + snc[col]     - 2.f * acc[mi][ni][h * 2],     0.f);
                float e1 = fmaxf(snr[row] + snc[col + 1] - 2.f * acc[mi][ni][h * 2 + 1], 0.f);
                float a0 = 1.f / (sqrtf(e0 + 1e-6f) + 1.f) - ABAR;
                float a1 = 1.f / (sqrtf(e1 + 1e-6f) + 1.f) - ABAR;
                *(__half2*)(smem + OFF_SAT + row * PR + col * 2) = __floats2half2_rn(a0, a1);
                acc[mi][ni][h * 2] = 0.f;
                acc[mi][ni][h * 2 + 1] = 0.f;
            }
        }
    }
    __syncthreads();

    // ---- stage 2 ----
    for (int kc = 0; kc < 4; kc++) {
        if (kc < 3) loadB(g_Wh, kc + 1, (kc + 1) & 1);
        CP_COMMIT();
        if (kc < 3) CP_WAIT1(); else CP_WAIT0();
        __syncthreads();
        uint32_t bufB = sD + (kc & 1) * BTILE;
#pragma unroll
        for (int kk = 0; kk < 4; kk++) {
            uint32_t af[2][4];
#pragma unroll
            for (int mi = 0; mi < 2; mi++)
                ldsm4(af[mi], sAt + (uint32_t)((m0 + mi * 16 + (lane & 15)) * PR
                                               + kc * 128 + kk * 32 + (lane >> 4) * 16));
            uint32_t bf[4][2];
#pragma unroll
            for (int np = 0; np < 2; np++) {
                uint32_t r[4];
                ldsm4(r, bufB + (uint32_t)((n0 + np * 16 + (lane & 7) + ((lane >> 4) & 1) * 8) * PB
                                            + kk * 32 + ((lane >> 3) & 1) * 16));
                bf[np * 2][0] = r[0]; bf[np * 2][1] = r[1];
                bf[np * 2 + 1][0] = r[2]; bf[np * 2 + 1][1] = r[3];
            }
#pragma unroll
            for (int mi = 0; mi < 2; mi++)
#pragma unroll
                for (int ni = 0; ni < 4; ni++)
                    mma_fp16(acc[mi][ni], af[mi], bf[ni]);
        }
        __syncthreads();
    }

    // ---- stage-2 epilogue: +corr, fp32 store, partial BN stats ----
    float ps = 0.f, pq = 0.f;
#pragma unroll
    for (int mi = 0; mi < 2; mi++) {
#pragma unroll
        for (int ni = 0; ni < 4; ni++) {
#pragma unroll
            for (int h = 0; h < 2; h++) {
                int row = m0 + mi * 16 + (lane >> 2) + h * 8;
                int col = n0 + ni * 8 + (lane & 3) * 2;
                float v0 = acc[mi][ni][h * 2]     + scorr[col];
                float v1 = acc[mi][ni][h * 2 + 1] + scorr[col + 1];
                *(float2*)&out[row * DIM + col] = make_float2(v0, v1);
                ps += v0 + v1;
                pq += v0 * v0 + v1 * v1;
            }
        }
    }
#pragma unroll
    for (int off = 16; off; off >>= 1) {
        ps += __shfl_xor_sync(0xffffffffu, ps, off);
        pq += __shfl_xor_sync(0xffffffffu, pq, off);
    }
    float* ws = (float*)(smem + OFF_STAT);
    float* wq = ws + 16;
    if (lane == 0) { ws[wid] = ps; wq[wid] = pq; }
    __syncthreads();
    if (t == 0) {
        float S = 0.f, Q = 0.f;
#pragma unroll
        for (int w = 0; w < 16; w++) { S += ws[w]; Q += wq[w]; }
        int slot = b * 4 + jb;
        if (which) { g_pa1s[slot] = S; g_pa1q[slot] = Q; }
        else       { g_pa3s[slot] = S; g_pa3q[slot] = Q; }
    }
}

// ---------------------------------------------------------------------------
// k_bn: reduce this block's channel partials, then apply BN.
// grid 1024 x 256. Block chunk = 4096 elements (1024 float4).
// Thread t: float4 indices chunk + t + i*256 (i=0..3): coalesced + MLP 4.
// out layout: [which_out(2)][b(16)][c(2)][s(256)][d(256)]
// ---------------------------------------------------------------------------
__global__ void __launch_bounds__(256) k_bn(const float* __restrict__ x1,
                                            const float* __restrict__ x2,
                                            const float* __restrict__ gamma,
                                            const float* __restrict__ beta,
                                            float* __restrict__ out) {
    int t = threadIdx.x;
    int e0 = blockIdx.x << 12;           // first element of chunk
    int which = e0 >> 21;
    int rem = e0 & ((1 << 21) - 1);
    int bb = rem >> 17;
    int c = (rem >> 16) & 1;
    int pos0 = rem & 65535;
    const float* src;
    int ch;
    if (which == 0) { src = c ? g_x1att : x1; ch = c ? 1 : 0; }
    else            { src = c ? g_x2att : x2; ch = c ? 3 : 2; }

    // ---- channel stats from fixed-slot partials ----
    __shared__ float rs[256], rq[256];
    float s = 0.f, q = 0.f;
    if (ch == 0)      { s = g_p1s[t] + g_p1s[t + 256]; q = g_p1q[t] + g_p1q[t + 256]; }
    else if (ch == 2) { s = g_p2s[t] + g_p2s[t + 256]; q = g_p2q[t] + g_p2q[t + 256]; }
    else if (ch == 1) { if (t < 64) { s = g_pa1s[t]; q = g_pa1q[t]; } }
    else              { if (t < 64) { s = g_pa3s[t]; q = g_pa3q[t]; } }
    rs[t] = s; rq[t] = q;
    __syncthreads();
#pragma unroll
    for (int off = 128; off; off >>= 1) {
        if (t < off) { rs[t] += rs[t + off]; rq[t] += rq[t + off]; }
        __syncthreads();
    }
    const float Ninv = 1.0f / (float)NTOT;
    float mean = rs[0] * Ninv;
    float var = rq[0] * Ninv - mean * mean;
    float sc = gamma[c] * rsqrtf(var + 1e-5f);
    float sh = beta[c] - mean * sc;

    // ---- apply: 4 coalesced float4 groups, MLP 4 ----
    const float4* s4 = (const float4*)&src[bb * MAT + pos0];
    float4* o4 = (float4*)&out[e0];
    float4 v[4];
#pragma unroll
    for (int i = 0; i < 4; i++) v[i] = s4[t + i * 256];
#pragma unroll
    for (int i = 0; i < 4; i++) {
        float4 o;
        o.x = v[i].x * sc + sh;
        o.y = v[i].y * sc + sh;
        o.z = v[i].z * sc + sh;
        o.w = v[i].w * sc + sh;
        o4[t + i * 256] = o;
    }
}

// ---------------------------------------------------------------------------
extern "C" void kernel_launch(void* const* d_in, const int* in_sizes, int n_in,
                              void* d_out, int out_size) {
    const float* x1    = (const float*)d_in[0];
    const float* x2    = (const float*)d_in[1];
    const float* W     = (const float*)d_in[2];
    const float* bias  = (const float*)d_in[3];
    const float* gamma = (const float*)d_in[4];
    const float* beta  = (const float*)d_in[5];
    float* out = (float*)d_out;

    cudaFuncSetAttribute(k_att, cudaFuncAttributeMaxDynamicSharedMemorySize, F_SMEM);

    k_prep<<<1120, 256>>>(x1, x2, W, bias);
    k_att<<<dim3(4, 32), 512, F_SMEM>>>();
    k_bn<<<1024, 256>>>(x1, x2, gamma, beta, out);
}

// round 10
// speedup vs baseline: 1.0837x; 1.0083x over previous
#include <cuda_runtime.h>
#include <cuda_fp16.h>
#include <stdint.h>

#define BATCH 16
#define SEQ 256
#define DIM 256
#define MAT 65536
#define NTOT 1048576
#define ABAR 0.042323627f   // 1/(1+sqrt(512))

// ---------------------------------------------------------------------------
// Device-global scratch (no atomics anywhere: fixed-slot partial sums)
// ---------------------------------------------------------------------------
__device__ float g_x1att[NTOT];
__device__ float g_x2att[NTOT];
__device__ float g_n1[BATCH*SEQ];
__device__ float g_n2[BATCH*SEQ];
__device__ float g_corr[DIM];  // ABAR*rowsum(W)+bias
__device__ __half g_x1h[NTOT];
__device__ __half g_x2h[NTOT];
__device__ __half g_Wh[SEQ*DIM];
// partial BN stats
__device__ float g_p1s[128], g_p1q[128];   // x1 (ch0), one per prep block
__device__ float g_p2s[128], g_p2q[128];   // x2 (ch2)
__device__ float g_pa1s[64], g_pa1q[64];   // x1_att (ch1), one per k_att CTA
__device__ float g_pa3s[64], g_pa3q[64];   // x2_att (ch3)

// ---------------------------------------------------------------------------
// Portable-ISA helpers (sm_80+)
// ---------------------------------------------------------------------------
__device__ __forceinline__ uint32_t smem_to_u32(const void* p) {
    uint32_t a;
    asm("{ .reg .u64 t; cvta.to.shared.u64 t, %1; cvt.u32.u64 %0, t; }" : "=r"(a) : "l"(p));
    return a;
}
__device__ __forceinline__ void ldsm4(uint32_t* r, uint32_t addr) {
    asm volatile("ldmatrix.sync.aligned.m8n8.x4.shared.b16 {%0,%1,%2,%3}, [%4];"
                 : "=r"(r[0]), "=r"(r[1]), "=r"(r[2]), "=r"(r[3]) : "r"(addr));
}
__device__ __forceinline__ void mma_fp16(float* c, const uint32_t* a, const uint32_t* b) {
    asm volatile("mma.sync.aligned.m16n8k16.row.col.f32.f16.f16.f32 "
                 "{%0,%1,%2,%3}, {%4,%5,%6,%7}, {%8,%9}, {%0,%1,%2,%3};"
                 : "+f"(c[0]), "+f"(c[1]), "+f"(c[2]), "+f"(c[3])
                 : "r"(a[0]), "r"(a[1]), "r"(a[2]), "r"(a[3]), "r"(b[0]), "r"(b[1]));
}
__device__ __forceinline__ void cp16(uint32_t saddr, const void* g) {
    asm volatile("cp.async.cg.shared.global [%0], [%1], 16;" :: "r"(saddr), "l"(g));
}
#define CP_COMMIT() asm volatile("cp.async.commit_group;" ::: "memory")
#define CP_WAIT1()  asm volatile("cp.async.wait_group 1;" ::: "memory")
#define CP_WAIT0()  asm volatile("cp.async.wait_group 0;" ::: "memory")

// SMEM geometry for the fused kernel (64-row blocks)
#define PR 528                  // pitch of 256-half rows (33x16B, conflict-free)
#define PB 144                  // pitch of 64-half rows
#define BTILE (256 * PB)        // 36864 bytes: one B chunk [256 n][64 k]
#define OFF_SNC   0             // 256 floats
#define OFF_SNR   1024          // 64 floats
#define OFF_CORR  1280          // 256 floats
#define OFF_SR    2304          // 64 x PR = 33792
#define OFF_SAT   36096         // 64 x PR = 33792
#define OFF_SD    69888         // 2 x BTILE = 73728
#define OFF_STAT  143616        // 32 floats
#define F_SMEM    143744

// ---------------------------------------------------------------------------
// k_prep: blocks [0,128) x1: norms+partial stats+fp16 (32 rows/block, 4/warp).
//         [128,256) x2.  [256,320) W fp16 convert.  [320,352) corr.
// ---------------------------------------------------------------------------
__global__ void __launch_bounds__(256) k_prep(const float* __restrict__ x1,
                                              const float* __restrict__ x2,
                                              const float* __restrict__ W,
                                              const float* __restrict__ bias) {
    int blk = blockIdx.x;
    int t = threadIdx.x;
    int warp = t >> 5, lane = t & 31;
    if (blk >= 320) {   // corr rows
        int o = (blk - 320) * 8 + warp;
        float s = 0.f;
#pragma unroll
        for (int c = 0; c < 8; c++) s += W[o * SEQ + lane + c * 32];
#pragma unroll
        for (int off = 16; off; off >>= 1) s += __shfl_xor_sync(0xffffffffu, s, off);
        if (lane == 0) g_corr[o] = ABAR * s + bias[o];
        return;
    }
    if (blk >= 256) {   // W fp16 (vectorized)
        int base = (blk - 256) * 1024 + t * 4;
        float4 v = *(const float4*)&W[base];
        __half2 h0 = __floats2half2_rn(v.x, v.y);
        __half2 h1 = __floats2half2_rn(v.z, v.w);
        *(uint2*)&g_Wh[base] = make_uint2(*(uint32_t*)&h0, *(uint32_t*)&h1);
        return;
    }
    const float* X;
    float* Nrm;
    __half* Xh;
    float* Ps;
    float* Pq;
    if (blk < 128) { X = x1; Nrm = g_n1; Xh = g_x1h; Ps = g_p1s; Pq = g_p1q; }
    else           { X = x2; Nrm = g_n2; Xh = g_x2h; blk -= 128; Ps = g_p2s; Pq = g_p2q; }
    int row0 = blk * 32 + warp * 4;
    const float4* X4 = (const float4*)X;
    // batch all 8 loads first: MLP 8
    float4 v[4][2];
#pragma unroll
    for (int r = 0; r < 4; r++) {
        v[r][0] = X4[(row0 + r) * 64 + lane];
        v[r][1] = X4[(row0 + r) * 64 + lane + 32];
    }
    float S = 0.f, Q = 0.f;
#pragma unroll
    for (int r = 0; r < 4; r++) {
        float4 a = v[r][0], b = v[r][1];
        float s = a.x + a.y + a.z + a.w + b.x + b.y + b.z + b.w;
        float q = a.x*a.x + a.y*a.y + a.z*a.z + a.w*a.w
                + b.x*b.x + b.y*b.y + b.z*b.z + b.w*b.w;
        __half2 h0 = __floats2half2_rn(a.x, a.y);
        __half2 h1 = __floats2half2_rn(a.z, a.w);
        __half2 h2 = __floats2half2_rn(b.x, b.y);
        __half2 h3 = __floats2half2_rn(b.z, b.w);
        uint2* dst = (uint2*)(Xh + (row0 + r) * DIM);
        dst[lane]      = make_uint2(*(uint32_t*)&h0, *(uint32_t*)&h1);
        dst[lane + 32] = make_uint2(*(uint32_t*)&h2, *(uint32_t*)&h3);
#pragma unroll
        for (int off = 16; off; off >>= 1) {
            s += __shfl_xor_sync(0xffffffffu, s, off);
            q += __shfl_xor_sync(0xffffffffu, q, off);
        }
        if (lane == 0) Nrm[row0 + r] = q;
        S += s; Q += q;
    }
    __shared__ float bs[8], bq[8];
    if (lane == 0) { bs[warp] = S; bq[warp] = Q; }
    __syncthreads();
    if (t == 0) {
        float SS = 0.f, QQ = 0.f;
#pragma unroll
        for (int w = 0; w < 8; w++) { SS += bs[w]; QQ += bq[w]; }
        Ps[blk] = SS;
        Pq[blk] = QQ;
    }
}

// ---------------------------------------------------------------------------
// k_att: FUSED attention + projection, 64-row blocks.
// grid (4, 32): x = j-block (64 rows), y = b*2+which.
//   which=0: rows from x2, cols from x1 -> x2_att rows (ch 3)
//   which=1: rows from x1, cols from x2 -> x1_att rows (ch 1)
// Stage 1: delta[r][i] (M=64,N=256,K=256) -> SMEM strip fp16
// Stage 2: out[r][o] = delta @ W^T + corr  (M=64,N=256,K=256)
// 512 threads, 16 warps: m = (wid&1)*32, n = (wid>>1)*32. Warp tile 32x32.
// ---------------------------------------------------------------------------
__global__ void __launch_bounds__(512, 1) k_att() {
    extern __shared__ char smem[];
    uint32_t sb = smem_to_u32(smem);
    float* snc   = (float*)(smem + OFF_SNC);
    float* snr   = (float*)(smem + OFF_SNR);
    float* scorr = (float*)(smem + OFF_CORR);
    int t = threadIdx.x, lane = t & 31, wid = t >> 5;
    int jb = blockIdx.x;
    int bz = blockIdx.y, b = bz >> 1, which = bz & 1;

    const __half* R = (which ? g_x1h : g_x2h) + b * MAT + jb * 64 * DIM;
    const __half* C = (which ? g_x2h : g_x1h) + b * MAT;
    const float* NR = (which ? g_n1 : g_n2) + b * SEQ + jb * 64;
    const float* NC = (which ? g_n2 : g_n1) + b * SEQ;
    float* out = (which ? g_x1att : g_x2att) + b * MAT + jb * 64 * DIM;

    if (t < 256) { snc[t] = NC[t]; scorr[t] = g_corr[t]; }
    else if (t < 320) snr[t - 256] = NR[t - 256];

    const uint32_t sR  = sb + OFF_SR;
    const uint32_t sAt = sb + OFF_SAT;
    const uint32_t sD  = sb + OFF_SD;

    auto loadB = [&](const __half* src, int kc, int buf) {
#pragma unroll
        for (int s = 0; s < 4; s++) {
            int seg = t + s * 512;
            int row = seg >> 3, c = seg & 7;
            cp16(sD + (uint32_t)(buf * BTILE + row * PB + c * 16),
                 src + row * SEQ + kc * 64 + c * 8);
        }
    };

#pragma unroll
    for (int s = 0; s < 4; s++) {
        int seg = t + s * 512;
        int row = seg >> 5, c = seg & 31;
        cp16(sR + (uint32_t)(row * PR + c * 16), R + row * DIM + c * 8);
    }
    loadB(C, 0, 0);
    CP_COMMIT();

    int m0 = (wid & 1) * 32, n0 = (wid >> 1) * 32;
    float acc[2][4][4] = {};

    // ---- stage 1 ----
    for (int kc = 0; kc < 4; kc++) {
        if (kc < 3) loadB(C, kc + 1, (kc + 1) & 1);
        else        loadB(g_Wh, 0, 0);          // prefetch W chunk 0
        CP_COMMIT();
        CP_WAIT1();
        __syncthreads();
        uint32_t bufB = sD + (kc & 1) * BTILE;
#pragma unroll
        for (int kk = 0; kk < 4; kk++) {
            uint32_t af[2][4];
#pragma unroll
            for (int mi = 0; mi < 2; mi++)
                ldsm4(af[mi], sR + (uint32_t)((m0 + mi * 16 + (lane & 15)) * PR
                                              + kc * 128 + kk * 32 + (lane >> 4) * 16));
            uint32_t bf[4][2];
#pragma unroll
            for (int np = 0; np < 2; np++) {
                uint32_t r[4];
                ldsm4(r, bufB + (uint32_t)((n0 + np * 16 + (lane & 7) + ((lane >> 4) & 1) * 8) * PB
                                            + kk * 32 + ((lane >> 3) & 1) * 16));
                bf[np * 2][0] = r[0]; bf[np * 2][1] = r[1];
                bf[np * 2 + 1][0] = r[2]; bf[np * 2 + 1][1] = r[3];
            }
#pragma unroll
            for (int mi = 0; mi < 2; mi++)
#pragma unroll
                for (int ni = 0; ni < 4; ni++)
                    mma_fp16(acc[mi][ni], af[mi], bf[ni]);
        }
        __syncthreads();
    }

    // ---- stage-1 epilogue: delta -> sAt ----
#pragma unroll
    for (int mi = 0; mi < 2; mi++) {
#pragma unroll
        for (int ni = 0; ni < 4; ni++) {
#pragma unroll
            for (int h = 0; h < 2; h++) {
                int row = m0 + mi * 16 + (lane >> 2) + h * 8;
                int col = n0 + ni * 8 + (lane & 3) * 2;
                float e0 = fmaxf(snr[row] + snc[col]     - 2.f * acc[mi][ni][h * 2],     0.f);
                float e1 = fmaxf(snr[row] + snc[col + 1] - 2.f * acc[mi][ni][h * 2 + 1], 0.f);
                float a0 = 1.f / (sqrtf(e0 + 1e-6f) + 1.f) - ABAR;
                float a1 = 1.f / (sqrtf(e1 + 1e-6f) + 1.f) - ABAR;
                *(__half2*)(smem + OFF_SAT + row * PR + col * 2) = __floats2half2_rn(a0, a1);
                acc[mi][ni][h * 2] = 0.f;
                acc[mi][ni][h * 2 + 1] = 0.f;
            }
        }
    }
    __syncthreads();

    // ---- stage 2 ----
    for (int kc = 0; kc < 4; kc++) {
        if (kc < 3) loadB(g_Wh, kc + 1, (kc + 1) & 1);
        CP_COMMIT();
        if (kc < 3) CP_WAIT1(); else CP_WAIT0();
        __syncthreads();
        uint32_t bufB = sD + (kc & 1) * BTILE;
#pragma unroll
        for (int kk = 0; kk < 4; kk++) {
            uint32_t af[2][4];
#pragma unroll
            for (int mi = 0; mi < 2; mi++)
                ldsm4(af[mi], sAt + (uint32_t)((m0 + mi * 16 + (lane & 15)) * PR
                                               + kc * 128 + kk * 32 + (lane >> 4) * 16));
            uint32_t bf[4][2];
#pragma unroll
            for (int np = 0; np < 2; np++) {
                uint32_t r[4];
                ldsm4(r, bufB + (uint32_t)((n0 + np * 16 + (lane & 7) + ((lane >> 4) & 1) * 8) * PB
                                            + kk * 32 + ((lane >> 3) & 1) * 16));
                bf[np * 2][0] = r[0]; bf[np * 2][1] = r[1];
                bf[np * 2 + 1][0] = r[2]; bf[np * 2 + 1][1] = r[3];
            }
#pragma unroll
            for (int mi = 0; mi < 2; mi++)
#pragma unroll
                for (int ni = 0; ni < 4; ni++)
                    mma_fp16(acc[mi][ni], af[mi], bf[ni]);
        }
        __syncthreads();
    }

    // ---- stage-2 epilogue: +corr, fp32 store, partial BN stats ----
    float ps = 0.f, pq = 0.f;
#pragma unroll
    for (int mi = 0; mi < 2; mi++) {
#pragma unroll
        for (int ni = 0; ni < 4; ni++) {
#pragma unroll
            for (int h = 0; h < 2; h++) {
                int row = m0 + mi * 16 + (lane >> 2) + h * 8;
                int col = n0 + ni * 8 + (lane & 3) * 2;
                float v0 = acc[mi][ni][h * 2]     + scorr[col];
                float v1 = acc[mi][ni][h * 2 + 1] + scorr[col + 1];
                *(float2*)&out[row * DIM + col] = make_float2(v0, v1);
                ps += v0 + v1;
                pq += v0 * v0 + v1 * v1;
            }
        }
    }
#pragma unroll
    for (int off = 16; off; off >>= 1) {
        ps += __shfl_xor_sync(0xffffffffu, ps, off);
        pq += __shfl_xor_sync(0xffffffffu, pq, off);
    }
    float* ws = (float*)(smem + OFF_STAT);
    float* wq = ws + 16;
    if (lane == 0) { ws[wid] = ps; wq[wid] = pq; }
    __syncthreads();
    if (t == 0) {
        float S = 0.f, Q = 0.f;
#pragma unroll
        for (int w = 0; w < 16; w++) { S += ws[w]; Q += wq[w]; }
        int slot = b * 4 + jb;
        if (which) { g_pa1s[slot] = S; g_pa1q[slot] = Q; }
        else       { g_pa3s[slot] = S; g_pa3q[slot] = Q; }
    }
}

// ---------------------------------------------------------------------------
// k_bn: reduce this block's channel partials, then apply BN.
// grid 512 x 256. Block chunk = 8192 elements (2048 float4).
// Thread t: float4 indices chunk + t + i*256 (i=0..7): coalesced + MLP 8.
// out layout: [which_out(2)][b(16)][c(2)][s(256)][d(256)]
// ---------------------------------------------------------------------------
__global__ void __launch_bounds__(256) k_bn(const float* __restrict__ x1,
                                            const float* __restrict__ x2,
                                            const float* __restrict__ gamma,
                                            const float* __restrict__ beta,
                                            float* __restrict__ out) {
    int t = threadIdx.x;
    int e0 = blockIdx.x << 13;           // first element of chunk (8192 elems)
    int which = e0 >> 21;
    int rem = e0 & ((1 << 21) - 1);
    int bb = rem >> 17;
    int c = (rem >> 16) & 1;
    int pos0 = rem & 65535;
    const float* src;
    int ch;
    if (which == 0) { src = c ? g_x1att : x1; ch = c ? 1 : 0; }
    else            { src = c ? g_x2att : x2; ch = c ? 3 : 2; }

    // ---- channel stats from fixed-slot partials ----
    __shared__ float rs[256], rq[256];
    float s = 0.f, q = 0.f;
    if (ch == 0)      { if (t < 128) { s = g_p1s[t]; q = g_p1q[t]; } }
    else if (ch == 2) { if (t < 128) { s = g_p2s[t]; q = g_p2q[t]; } }
    else if (ch == 1) { if (t < 64)  { s = g_pa1s[t]; q = g_pa1q[t]; } }
    else              { if (t < 64)  { s = g_pa3s[t]; q = g_pa3q[t]; } }
    rs[t] = s; rq[t] = q;
    __syncthreads();
#pragma unroll
    for (int off = 128; off; off >>= 1) {
        if (t < off) { rs[t] += rs[t + off]; rq[t] += rq[t + off]; }
        __syncthreads();
    }
    const float Ninv = 1.0f / (float)NTOT;
    float mean = rs[0] * Ninv;
    float var = rq[0] * Ninv - mean * mean;
    float sc = gamma[c] * rsqrtf(var + 1e-5f);
    float sh = beta[c] - mean * sc;

    // ---- apply: 8 coalesced float4 groups, MLP 8 ----
    const float4* s4 = (const float4*)&src[bb * MAT + pos0];
    float4* o4 = (float4*)&out[e0];
    float4 v[8];
#pragma unroll
    for (int i = 0; i < 8; i++) v[i] = s4[t + i * 256];
#pragma unroll
    for (int i = 0; i < 8; i++) {
        float4 o;
        o.x = v[i].x * sc + sh;
        o.y = v[i].y * sc + sh;
        o.z = v[i].z * sc + sh;
        o.w = v[i].w * sc + sh;
        o4[t + i * 256] = o;
    }
}

// ---------------------------------------------------------------------------
extern "C" void kernel_launch(void* const* d_in, const int* in_sizes, int n_in,
                              void* d_out, int out_size) {
    const float* x1    = (const float*)d_in[0];
    const float* x2    = (const float*)d_in[1];
    const float* W     = (const float*)d_in[2];
    const float* bias  = (const float*)d_in[3];
    const float* gamma = (const float*)d_in[4];
    const float* beta  = (const float*)d_in[5];
    float* out = (float*)d_out;

    cudaFuncSetAttribute(k_att, cudaFuncAttributeMaxDynamicSharedMemorySize, F_SMEM);

    k_prep<<<352, 256>>>(x1, x2, W, bias);
    k_att<<<dim3(4, 32), 512, F_SMEM>>>();
    k_bn<<<512, 256>>>(x1, x2, gamma, beta, out);
}

// round 12
// speedup vs baseline: 1.1618x; 1.0721x over previous
#include <cuda_runtime.h>
#include <cuda_fp16.h>
#include <stdint.h>

#define BATCH 16
#define SEQ 256
#define DIM 256
#define MAT 65536
#define NTOT 1048576
#define ABAR 0.042323627f   // 1/(1+sqrt(512))

// ---------------------------------------------------------------------------
// Device-global scratch (no atomics anywhere: fixed-slot partial sums)
// ---------------------------------------------------------------------------
__device__ float g_x1att[NTOT];
__device__ float g_x2att[NTOT];
__device__ float g_n1[BATCH*SEQ];
__device__ float g_n2[BATCH*SEQ];
__device__ float g_corr[DIM];  // ABAR*rowsum(W)+bias
__device__ __half g_x1h[NTOT];
__device__ __half g_x2h[NTOT];
__device__ __half g_Wh[SEQ*DIM];
// partial BN stats
__device__ float g_p1s[512], g_p1q[512];   // x1 (ch0), one per prep block
__device__ float g_p2s[512], g_p2q[512];   // x2 (ch2)
__device__ float g_pa1s[64], g_pa1q[64];   // x1_att (ch1), one per att CTA
__device__ float g_pa3s[64], g_pa3q[64];   // x2_att (ch3)

// ---------------------------------------------------------------------------
// Portable-ISA helpers (sm_80+)
// ---------------------------------------------------------------------------
__device__ __forceinline__ uint32_t smem_to_u32(const void* p) {
    uint32_t a;
    asm("{ .reg .u64 t; cvta.to.shared.u64 t, %1; cvt.u32.u64 %0, t; }" : "=r"(a) : "l"(p));
    return a;
}
__device__ __forceinline__ void ldsm4(uint32_t* r, uint32_t addr) {
    asm volatile("ldmatrix.sync.aligned.m8n8.x4.shared.b16 {%0,%1,%2,%3}, [%4];"
                 : "=r"(r[0]), "=r"(r[1]), "=r"(r[2]), "=r"(r[3]) : "r"(addr));
}
__device__ __forceinline__ void mma_fp16(float* c, const uint32_t* a, const uint32_t* b) {
    asm volatile("mma.sync.aligned.m16n8k16.row.col.f32.f16.f16.f32 "
                 "{%0,%1,%2,%3}, {%4,%5,%6,%7}, {%8,%9}, {%0,%1,%2,%3};"
                 : "+f"(c[0]), "+f"(c[1]), "+f"(c[2]), "+f"(c[3])
                 : "r"(a[0]), "r"(a[1]), "r"(a[2]), "r"(a[3]), "r"(b[0]), "r"(b[1]));
}
__device__ __forceinline__ void cp16(uint32_t saddr, const void* g) {
    asm volatile("cp.async.cg.shared.global [%0], [%1], 16;" :: "r"(saddr), "l"(g));
}
#define CP_COMMIT() asm volatile("cp.async.commit_group;" ::: "memory")
#define CP_WAIT1()  asm volatile("cp.async.wait_group 1;" ::: "memory")
#define CP_WAIT0()  asm volatile("cp.async.wait_group 0;" ::: "memory")

// SMEM geometry for the fused kernel (64-row blocks)
#define PR 528                  // pitch of 256-half rows (33x16B, conflict-free)
#define PB 144                  // pitch of 64-half rows
#define BTILE (256 * PB)        // 36864 bytes: one B chunk [256 n][64 k]
#define OFF_SNC   0             // 256 floats
#define OFF_SNR   1024          // 64 floats
#define OFF_CORR  1280          // 256 floats
#define OFF_SR    2304          // 64 x PR = 33792
#define OFF_SAT   36096         // 64 x PR = 33792
#define OFF_SD    69888         // 2 x BTILE = 73728
#define OFF_STAT  143616        // 32 floats
#define F_SMEM    143744

// ---------------------------------------------------------------------------
// k_prep (R9 form): blocks [0,512) x1: norms+partial stats+fp16.
//   [512,1024) x2.  [1024,1088) W fp16.  [1088,1120) corr.
// ---------------------------------------------------------------------------
__global__ void __launch_bounds__(256) k_prep(const float* __restrict__ x1,
                                              const float* __restrict__ x2,
                                              const float* __restrict__ W,
                                              const float* __restrict__ bias) {
    int blk = blockIdx.x;
    int t = threadIdx.x;
    if (blk >= 1088) {   // corr rows
        int warp = t >> 5, lane = t & 31;
        int o = (blk - 1088) * 8 + warp;
        float s = 0.f;
#pragma unroll
        for (int c = 0; c < 8; c++) s += W[o * SEQ + lane + c * 32];
#pragma unroll
        for (int off = 16; off; off >>= 1) s += __shfl_xor_sync(0xffffffffu, s, off);
        if (lane == 0) g_corr[o] = ABAR * s + bias[o];
        return;
    }
    if (blk >= 1024) {   // W fp16 (vectorized)
        int base = (blk - 1024) * 1024 + t * 4;
        float4 v = *(const float4*)&W[base];
        __half2 h0 = __floats2half2_rn(v.x, v.y);
        __half2 h1 = __floats2half2_rn(v.z, v.w);
        *(uint2*)&g_Wh[base] = make_uint2(*(uint32_t*)&h0, *(uint32_t*)&h1);
        return;
    }
    const float* X;
    float* Nrm;
    __half* Xh;
    float* Ps;
    float* Pq;
    if (blk < 512) { X = x1; Nrm = g_n1; Xh = g_x1h; Ps = g_p1s; Pq = g_p1q; }
    else           { X = x2; Nrm = g_n2; Xh = g_x2h; blk -= 512; Ps = g_p2s; Pq = g_p2q; }
    int warp = t >> 5, lane = t & 31;
    int row = blk * 8 + warp;
    const float4* p4 = (const float4*)(X + row * DIM);
    float4 v0 = p4[lane];
    float4 v1 = p4[lane + 32];
    float s = v0.x + v0.y + v0.z + v0.w + v1.x + v1.y + v1.z + v1.w;
    float q = v0.x*v0.x + v0.y*v0.y + v0.z*v0.z + v0.w*v0.w
            + v1.x*v1.x + v1.y*v1.y + v1.z*v1.z + v1.w*v1.w;
    {
        __half2 a0 = __floats2half2_rn(v0.x, v0.y);
        __half2 a1 = __floats2half2_rn(v0.z, v0.w);
        __half2 b0 = __floats2half2_rn(v1.x, v1.y);
        __half2 b1 = __floats2half2_rn(v1.z, v1.w);
        uint2* dst = (uint2*)(Xh + row * DIM);
        dst[lane]      = make_uint2(*(uint32_t*)&a0, *(uint32_t*)&a1);
        dst[lane + 32] = make_uint2(*(uint32_t*)&b0, *(uint32_t*)&b1);
    }
#pragma unroll
    for (int off = 16; off; off >>= 1) {
        s += __shfl_xor_sync(0xffffffffu, s, off);
        q += __shfl_xor_sync(0xffffffffu, q, off);
    }
    __shared__ float bs[8], bq[8];
    if (lane == 0) { Nrm[row] = q; bs[warp] = s; bq[warp] = q; }
    __syncthreads();
    if (t == 0) {
        float S = 0.f, Q = 0.f;
#pragma unroll
        for (int w = 0; w < 8; w++) { S += bs[w]; Q += bq[w]; }
        Ps[blk] = S;
        Pq[blk] = Q;
    }
}

// ---------------------------------------------------------------------------
// k_att: heterogeneous launch, grid 192 x 512 threads.
//  CTAs [0,128): FUSED attention + projection (64-row blocks) — the 128
//    tiles jb(4) x b(16) x which(2), indexed exactly as R10's (4,32) grid.
//  CTAs [128,192): BN-apply for channels 0/2 (raw x1/x2 half of output) —
//    depends only on k_prep, so it overlaps / backfills around att CTAs.
// ---------------------------------------------------------------------------
__global__ void __launch_bounds__(512, 1) k_att(const float* __restrict__ x1,
                                                const float* __restrict__ x2,
                                                const float* __restrict__ gamma,
                                                const float* __restrict__ beta,
                                                float* __restrict__ outp) {
    extern __shared__ char smem[];
    uint32_t sb = smem_to_u32(smem);
    int t = threadIdx.x, lane = t & 31, wid = t >> 5;

    if (blockIdx.x >= 128) {
        // ===== bn02 path: unit = (which, bb, half-32K) =====
        int u = blockIdx.x - 128;           // 0..63
        int unit = u >> 1, half = u & 1;
        int which = unit >> 4, bb = unit & 15;
        const float* src = which ? x2 : x1;
        const float* Ps = which ? g_p2s : g_p1s;
        const float* Pq = which ? g_p2q : g_p1q;
        __shared__ float rs[512], rq[512];
        rs[t] = Ps[t]; rq[t] = Pq[t];
        __syncthreads();
#pragma unroll
        for (int off = 256; off; off >>= 1) {
            if (t < off) { rs[t] += rs[t + off]; rq[t] += rq[t + off]; }
            __syncthreads();
        }
        const float Ninv = 1.0f / (float)NTOT;
        float mean = rs[0] * Ninv;
        float var = rq[0] * Ninv - mean * mean;
        float sc = gamma[0] * rsqrtf(var + 1e-5f);
        float sh = beta[0] - mean * sc;
        // apply 32768 elements: 16 float4/thread, two MLP-8 batches
        int e0 = (which << 21) + (bb << 17) + half * 32768;
        const float4* s4 = (const float4*)&src[bb * MAT + half * 32768];
        float4* o4 = (float4*)&outp[e0];
#pragma unroll
        for (int g = 0; g < 2; g++) {
            float4 v[8];
#pragma unroll
            for (int i = 0; i < 8; i++) v[i] = s4[t + (g * 8 + i) * 512];
#pragma unroll
            for (int i = 0; i < 8; i++) {
                float4 o;
                o.x = v[i].x * sc + sh;
                o.y = v[i].y * sc + sh;
                o.z = v[i].z * sc + sh;
                o.w = v[i].w * sc + sh;
                o4[t + (g * 8 + i) * 512] = o;
            }
        }
        return;
    }

    // ===== att path: 128 tiles = jb(4) x (b*2+which)(32) =====
    float* snc   = (float*)(smem + OFF_SNC);
    float* snr   = (float*)(smem + OFF_SNR);
    float* scorr = (float*)(smem + OFF_CORR);
    int jb = blockIdx.x & 3;
    int bz = blockIdx.x >> 2;            // 0..31
    int b = bz >> 1, which = bz & 1;

    const __half* R = (which ? g_x1h : g_x2h) + b * MAT + jb * 64 * DIM;
    const __half* C = (which ? g_x2h : g_x1h) + b * MAT;
    const float* NR = (which ? g_n1 : g_n2) + b * SEQ + jb * 64;
    const float* NC = (which ? g_n2 : g_n1) + b * SEQ;
    float* out = (which ? g_x1att : g_x2att) + b * MAT + jb * 64 * DIM;

    if (t < 256) { snc[t] = NC[t]; scorr[t] = g_corr[t]; }
    else if (t < 320) snr[t - 256] = NR[t - 256];

    const uint32_t sR  = sb + OFF_SR;
    const uint32_t sAt = sb + OFF_SAT;
    const uint32_t sD  = sb + OFF_SD;

    auto loadB = [&](const __half* src, int kc, int buf) {
#pragma unroll
        for (int s = 0; s < 4; s++) {
            int seg = t + s * 512;
            int row = seg >> 3, c = seg & 7;
            cp16(sD + (uint32_t)(buf * BTILE + row * PB + c * 16),
                 src + row * SEQ + kc * 64 + c * 8);
        }
    };

#pragma unroll
    for (int s = 0; s < 4; s++) {
        int seg = t + s * 512;
        int row = seg >> 5, c = seg & 31;
        cp16(sR + (uint32_t)(row * PR + c * 16), R + row * DIM + c * 8);
    }
    loadB(C, 0, 0);
    CP_COMMIT();

    int m0 = (wid & 1) * 32, n0 = (wid >> 1) * 32;
    float acc[2][4][4] = {};

    // ---- stage 1 ----
    for (int kc = 0; kc < 4; kc++) {
        if (kc < 3) loadB(C, kc + 1, (kc + 1) & 1);
        else        loadB(g_Wh, 0, 0);          // prefetch W chunk 0
        CP_COMMIT();
        CP_WAIT1();
        __syncthreads();
        uint32_t bufB = sD + (kc & 1) * BTILE;
#pragma unroll
        for (int kk = 0; kk < 4; kk++) {
            uint32_t af[2][4];
#pragma unroll
            for (int mi = 0; mi < 2; mi++)
                ldsm4(af[mi], sR + (uint32_t)((m0 + mi * 16 + (lane & 15)) * PR
                                              + kc * 128 + kk * 32 + (lane >> 4) * 16));
            uint32_t bf[4][2];
#pragma unroll
            for (int np = 0; np < 2; np++) {
                uint32_t r[4];
                ldsm4(r, bufB + (uint32_t)((n0 + np * 16 + (lane & 7) + ((lane >> 4) & 1) * 8) * PB
                                            + kk * 32 + ((lane >> 3) & 1) * 16));
                bf[np * 2][0] = r[0]; bf[np * 2][1] = r[1];
                bf[np * 2 + 1][0] = r[2]; bf[np * 2 + 1][1] = r[3];
            }
#pragma unroll
            for (int mi = 0; mi < 2; mi++)
#pragma unroll
                for (int ni = 0; ni < 4; ni++)
                    mma_fp16(acc[mi][ni], af[mi], bf[ni]);
        }
        __syncthreads();
    }

    // ---- stage-1 epilogue: delta -> sAt ----
#pragma unroll
    for (int mi = 0; mi < 2; mi++) {
#pragma unroll
        for (int ni = 0; ni < 4; ni++) {
#pragma unroll
            for (int h = 0; h < 2; h++) {
                int row = m0 + mi * 16 + (lane >> 2) + h * 8;
                int col = n0 + ni * 8 + (lane & 3) * 2;
                float e0 = fmaxf(snr[row] + snc[col]     - 2.f * acc[mi][ni][h * 2],     0.f);
                float e1 = fmaxf(snr[row] + snc[col + 1] - 2.f * acc[mi][ni][h * 2 + 1], 0.f);
                float a0 = 1.f / (sqrtf(e0 + 1e-6f) + 1.f) - ABAR;
                float a1 = 1.f / (sqrtf(e1 + 1e-6f) + 1.f) - ABAR;
                *(__half2*)(smem + OFF_SAT + row * PR + col * 2) = __floats2half2_rn(a0, a1);
                acc[mi][ni][h * 2] = 0.f;
                acc[mi][ni][h * 2 + 1] = 0.f;
            }
        }
    }
    __syncthreads();

    // ---- stage 2 ----
    for (int kc = 0; kc < 4; kc++) {
        if (kc < 3) loadB(g_Wh, kc + 1, (kc + 1) & 1);
        CP_COMMIT();
        if (kc < 3) CP_WAIT1(); else CP_WAIT0();
        __syncthreads();
        uint32_t bufB = sD + (kc & 1) * BTILE;
#pragma unroll
        for (int kk = 0; kk < 4; kk++) {
            uint32_t af[2][4];
#pragma unroll
            for (int mi = 0; mi < 2; mi++)
                ldsm4(af[mi], sAt + (uint32_t)((m0 + mi * 16 + (lane & 15)) * PR
                                               + kc * 128 + kk * 32 + (lane >> 4) * 16));
            uint32_t bf[4][2];
#pragma unroll
            for (int np = 0; np < 2; np++) {
                uint32_t r[4];
                ldsm4(r, bufB + (uint32_t)((n0 + np * 16 + (lane & 7) + ((lane >> 4) & 1) * 8) * PB
                                            + kk * 32 + ((lane >> 3) & 1) * 16));
                bf[np * 2][0] = r[0]; bf[np * 2][1] = r[1];
                bf[np * 2 + 1][0] = r[2]; bf[np * 2 + 1][1] = r[3];
            }
#pragma unroll
            for (int mi = 0; mi < 2; mi++)
#pragma unroll
                for (int ni = 0; ni < 4; ni++)
                    mma_fp16(acc[mi][ni], af[mi], bf[ni]);
        }
        __syncthreads();
    }

    // ---- stage-2 epilogue: +corr, fp32 store, partial BN stats ----
    float ps = 0.f, pq = 0.f;
#pragma unroll
    for (int mi = 0; mi < 2; mi++) {
#pragma unroll
        for (int ni = 0; ni < 4; ni++) {
#pragma unroll
            for (int h = 0; h < 2; h++) {
                int row = m0 + mi * 16 + (lane >> 2) + h * 8;
                int col = n0 + ni * 8 + (lane & 3) * 2;
                float v0 = acc[mi][ni][h * 2]     + scorr[col];
                float v1 = acc[mi][ni][h * 2 + 1] + scorr[col + 1];
                *(float2*)&out[row * DIM + col] = make_float2(v0, v1);
                ps += v0 + v1;
                pq += v0 * v0 + v1 * v1;
            }
        }
    }
#pragma unroll
    for (int off = 16; off; off >>= 1) {
        ps += __shfl_xor_sync(0xffffffffu, ps, off);
        pq += __shfl_xor_sync(0xffffffffu, pq, off);
    }
    float* ws = (float*)(smem + OFF_STAT);
    float* wq = ws + 16;
    if (lane == 0) { ws[wid] = ps; wq[wid] = pq; }
    __syncthreads();
    if (t == 0) {
        float S = 0.f, Q = 0.f;
#pragma unroll
        for (int w = 0; w < 16; w++) { S += ws[w]; Q += wq[w]; }
        int slot = b * 4 + jb;
        if (which) { g_pa1s[slot] = S; g_pa1q[slot] = Q; }
        else       { g_pa3s[slot] = S; g_pa3q[slot] = Q; }
    }
}

// ---------------------------------------------------------------------------
// k_bn13: BN-apply for channels 1/3 (att half of output, 16MB).
// grid 256 x 256: block = (which, bb, chunk of 8192 in c=1 plane).
// ---------------------------------------------------------------------------
__global__ void __launch_bounds__(256) k_bn13(const float* __restrict__ gamma,
                                              const float* __restrict__ beta,
                                              float* __restrict__ outp) {
    int t = threadIdx.x;
    int u = blockIdx.x;                  // 0..255
    int which = u >> 7;
    int bb = (u >> 3) & 15;
    int chunk = u & 7;
    const float* src = which ? g_x2att : g_x1att;
    const float* Ps = which ? g_pa3s : g_pa1s;
    const float* Pq = which ? g_pa3q : g_pa1q;

    __shared__ float rs[256], rq[256];
    float s = 0.f, q = 0.f;
    if (t < 64) { s = Ps[t]; q = Pq[t]; }
    rs[t] = s; rq[t] = q;
    __syncthreads();
#pragma unroll
    for (int off = 32; off; off >>= 1) {
        if (t < off) { rs[t] += rs[t + off]; rq[t] += rq[t + off]; }
        __syncthreads();
    }
    const float Ninv = 1.0f / (float)NTOT;
    float mean = rs[0] * Ninv;
    float var = rq[0] * Ninv - mean * mean;
    float sc = gamma[1] * rsqrtf(var + 1e-5f);
    float sh = beta[1] - mean * sc;

    int pos = chunk * 8192;
    int e0 = (which << 21) + (bb << 17) + 65536 + pos;
    const float4* s4 = (const float4*)&src[bb * MAT + pos];
    float4* o4 = (float4*)&outp[e0];
    float4 v[8];
#pragma unroll
    for (int i = 0; i < 8; i++) v[i] = s4[t + i * 256];
#pragma unroll
    for (int i = 0; i < 8; i++) {
        float4 o;
        o.x = v[i].x * sc + sh;
        o.y = v[i].y * sc + sh;
        o.z = v[i].z * sc + sh;
        o.w = v[i].w * sc + sh;
        o4[t + i * 256] = o;
    }
}

// ---------------------------------------------------------------------------
extern "C" void kernel_launch(void* const* d_in, const int* in_sizes, int n_in,
                              void* d_out, int out_size) {
    const float* x1    = (const float*)d_in[0];
    const float* x2    = (const float*)d_in[1];
    const float* W     = (const float*)d_in[2];
    const float* bias  = (const float*)d_in[3];
    const float* gamma = (const float*)d_in[4];
    const float* beta  = (const float*)d_in[5];
    float* out = (float*)d_out;

    cudaFuncSetAttribute(k_att, cudaFuncAttributeMaxDynamicSharedMemorySize, F_SMEM);

    k_prep<<<1120, 256>>>(x1, x2, W, bias);
    k_att<<<192, 512, F_SMEM>>>(x1, x2, gamma, beta, out);
    k_bn13<<<256, 256>>>(gamma, beta, out);
}